// round 2
// baseline (speedup 1.0000x reference)
#include <cuda_runtime.h>
#include <math.h>

#define NGROUPS   4
#define NPERG     10
#define NFILT     40
#define TIME_LEN  64000
#define BATCH     32
#define POOLSZ    401
#define POOLSTR   160
#define OUT_T     400
#define MAX_K     512
#define MAX_WS    512

// Scratch (static device globals — allowed; runtime alloc is not)
__device__ float g_kern[NGROUPS][MAX_K * 20];      // [tap][cos f0..9, sin f0..9]
__device__ float g_win [NGROUPS][MAX_WS * NPERG];  // [tap][f]
__device__ float g_mid [4ll * BATCH * TIME_LEN * NPERG];  // worst case all cs=1

struct MetaAll {
    int a[4], cs[4], ps[4], k[4], ws[4], Tg[4];
    long long off[4];
};

// ---------------------------------------------------------------------------
// Precompute Gabor kernels + pooling windows (double precision: immune to
// fast-math trig at large phase arguments; cost negligible).
// ---------------------------------------------------------------------------
__global__ void precompute_kernel(const float* __restrict__ cf_in,
                                  const float* __restrict__ bw_in,
                                  const float* __restrict__ pw_in,
                                  MetaAll meta) {
    const int g  = blockIdx.x;
    const int a  = meta.a[g];
    const int k  = meta.k[g];
    const int ws = meta.ws[g];
    const int cs = meta.cs[g];
    const double PI = 3.14159265358979323846;
    const double Zd = sqrt(2.0 * log(2.0)) / PI;

    for (int idx = threadIdx.x; idx < k * 20; idx += blockDim.x) {
        int i = idx / 20, j = idx % 20;
        int f = j % 10;
        float cff = fminf(fmaxf(cf_in[a + f], 0.f), (float)PI);
        float bwf = fminf(fmaxf(bw_in[a + f], (float)(2.0 * Zd)), (float)(401.0 * Zd));
        double t  = (double)(i - k / 2);
        double bw = (double)bwf;
        double gauss = exp(-t * t / (2.0 * bw * bw));
        double norm  = 1.0 / (sqrt(2.0 * PI) * bw);
        double ph    = t * (double)cff;
        double v     = norm * gauss * (j < 10 ? cos(ph) : sin(ph));
        g_kern[g][idx] = (float)v;
    }
    for (int idx = threadIdx.x; idx < ws * 10; idx += blockDim.x) {
        int j = idx / 10, f = idx % 10;
        float pwf = fminf(fmaxf(pw_in[a + f], (float)(2.0 / 401.0)), 0.5f);
        double sigma = (double)pwf / (double)cs * 401.0 / (double)ws;
        double hw = 0.5 * (double)(ws - 1);
        double u  = ((double)j - hw) / (sigma * hw);
        g_win[g][idx] = (float)exp(-0.5 * u * u);
    }
}

// ---------------------------------------------------------------------------
// Gabor conv + modulus^2. 128 threads, 256 outputs/block (2 per thread).
// x tile + coefficients staged in shared; coefficients loaded as broadcast
// float4 (5 per tap) -> 40 FMA per tap per thread pair.
// ---------------------------------------------------------------------------
__global__ void __launch_bounds__(128) conv_kernel(
        const float* __restrict__ x, int g, long long off,
        int cs, int k, int Tg) {
    extern __shared__ float sm[];
    float* skern = sm;              // k*20 floats (16B-aligned: 80B per tap)
    float* sx    = sm + k * 20;     // 256*cs + k floats

    const int tid = threadIdx.x;
    const int b   = blockIdx.y;
    const int w0  = blockIdx.x * 256;

    const float* kg = g_kern[g];
    for (int i = tid; i < k * 20; i += 128) skern[i] = kg[i];

    const int nx = 256 * cs + k;
    const float* xb = x + (long long)b * TIME_LEN;
    const int base = w0 * cs - (k >> 1);
    for (int i = tid; i < nx; i += 128) {
        int gx = base + i;
        sx[i] = ((unsigned)gx < (unsigned)TIME_LEN) ? xb[gx] : 0.f;
    }
    __syncthreads();

    float a0[20], a1[20];
#pragma unroll
    for (int j = 0; j < 20; ++j) { a0[j] = 0.f; a1[j] = 0.f; }

    const float4* k4 = (const float4*)skern;
    const float* p0 = sx + tid * cs;
    const float* p1 = sx + (tid + 128) * cs;

    for (int i = 0; i < k; ++i) {
        float x0 = p0[i];
        float x1 = p1[i];
#pragma unroll
        for (int q = 0; q < 5; ++q) {
            float4 c = k4[i * 5 + q];
            a0[q*4+0] = fmaf(x0, c.x, a0[q*4+0]);
            a0[q*4+1] = fmaf(x0, c.y, a0[q*4+1]);
            a0[q*4+2] = fmaf(x0, c.z, a0[q*4+2]);
            a0[q*4+3] = fmaf(x0, c.w, a0[q*4+3]);
            a1[q*4+0] = fmaf(x1, c.x, a1[q*4+0]);
            a1[q*4+1] = fmaf(x1, c.y, a1[q*4+1]);
            a1[q*4+2] = fmaf(x1, c.z, a1[q*4+2]);
            a1[q*4+3] = fmaf(x1, c.w, a1[q*4+3]);
        }
    }

    float* mid = g_mid + off;
    int wA = w0 + tid, wB = w0 + tid + 128;
    if (wA < Tg) {
        float* o = mid + ((long long)b * Tg + wA) * 10;
#pragma unroll
        for (int f = 0; f < 10; ++f) o[f] = a0[f] * a0[f] + a0[f + 10] * a0[f + 10];
    }
    if (wB < Tg) {
        float* o = mid + ((long long)b * Tg + wB) * 10;
#pragma unroll
        for (int f = 0; f < 10; ++f) o[f] = a1[f] * a1[f] + a1[f + 10] * a1[f + 10];
    }
}

// ---------------------------------------------------------------------------
// Depthwise Gaussian pooling. One thread per (b, p, f).
// ---------------------------------------------------------------------------
__global__ void pool_kernel(float* __restrict__ out, int g, long long off,
                            int ps, int ws, int Tg, int a) {
    extern __shared__ float swin[];
    const float* wg = g_win[g];
    for (int i = threadIdx.x; i < ws * 10; i += blockDim.x) swin[i] = wg[i];
    __syncthreads();

    int idx = blockIdx.x * blockDim.x + threadIdx.x;
    if (idx >= BATCH * OUT_T * NPERG) return;
    int f = idx % 10;
    int p = (idx / 10) % OUT_T;
    int b = idx / (OUT_T * 10);

    const float* m = g_mid + off + (long long)b * Tg * 10 + f;
    int t0 = p * ps - ws / 2;
    int jlo = (t0 < 0) ? -t0 : 0;
    int jhi = (t0 + ws > Tg) ? (Tg - t0) : ws;
    float acc = 0.f;
    for (int j = jlo; j < jhi; ++j)
        acc = fmaf(swin[j * 10 + f], m[(long long)(t0 + j) * 10], acc);

    out[((long long)b * OUT_T + p) * 40 + a + f] = acc;
}

// ---------------------------------------------------------------------------
// Host: replicate _mel_gabor_init + _group_meta exactly (numpy float64 path,
// cast to float32 where the reference does).
// ---------------------------------------------------------------------------
static void build_meta(MetaAll& m) {
    const double PI = 3.14159265358979323846;
    double freqs[257];
    for (int i = 0; i < 257; ++i) freqs[i] = 8000.0 * (double)i / 256.0;
    auto hz2mel = [](double f) { return 2595.0 * log10(1.0 + f / 700.0); };
    auto mel2hz = [](double mm) { return 700.0 * (pow(10.0, mm / 2595.0) - 1.0); };
    double mlo = hz2mel(60.0), mhi = hz2mel(7800.0);
    double hz[42];
    for (int i = 0; i < 42; ++i) hz[i] = mel2hz(mlo + (mhi - mlo) * (double)i / 41.0);

    const double Zd = sqrt(2.0 * log(2.0)) / PI;
    float cff[NFILT], bwf[NFILT];
    for (int i = 0; i < NFILT; ++i) {
        double l = hz[i], c = hz[i + 1], r = hz[i + 2];
        double peak = -1.0; int cb = 0;
        double vals[257];
        for (int j = 0; j < 257; ++j) {
            double v = (freqs[j] - l) / (c - l);
            double v2 = (r - freqs[j]) / (r - c);
            if (v2 < v) v = v2;
            if (v < 0.0) v = 0.0;
            vals[j] = sqrt(v);
            if (vals[j] > peak) { peak = vals[j]; cb = j; }
        }
        int fwhm = 0;
        for (int j = 0; j < 257; ++j) if (vals[j] >= 0.5 * peak) fwhm++;
        float cfv = (float)((double)cb * 2.0 * PI / 512.0);
        float bwv = (float)(sqrt(2.0 * log(2.0)) * 512.0 / (PI * (double)fwhm));
        // jnp.clip in float32
        cfv = fminf(fmaxf(cfv, 0.f), (float)PI);
        bwv = fminf(fmaxf(bwv, (float)(2.0 * Zd)), (float)(401.0 * Zd));
        cff[i] = cfv; bwf[i] = bwv;
    }

    const int divs[12] = {1, 2, 4, 5, 8, 10, 16, 20, 32, 40, 80, 160};
    long long off = 0;
    for (int g = 0; g < NGROUPS; ++g) {
        int a = g * NPERG, b = a + NPERG;
        float cmax = -1.f, bmax = -1.f;
        for (int i = a; i < b; ++i) {
            if (cff[i] > cmax) cmax = cff[i];
            if (bwf[i] > bmax) bmax = bwf[i];
        }
        double s = PI / (double)cmax;          // STRIDE_FACTOR = 1
        if (s < 1.0) s = 1.0;
        int cs = 1;
        for (int d = 0; d < 12; ++d) if ((double)divs[d] <= s) cs = divs[d];
        int k = (int)((double)bmax * 3.0);
        k += 1 - (k % 2);
        int ws = (int)(401.0 / (double)cs + 0.5);
        ws += 1 - (ws % 2);
        if (k > MAX_K - 1) k = MAX_K - 1;      // safety (never hit: bw clip caps k at 451)
        if (ws > MAX_WS - 1) ws = MAX_WS - 1;
        m.a[g] = a; m.cs[g] = cs; m.ps[g] = POOLSTR / cs;
        m.k[g] = k; m.ws[g] = ws; m.Tg[g] = TIME_LEN / cs;
        m.off[g] = off;
        off += (long long)BATCH * (TIME_LEN / cs) * NPERG;
    }
}

extern "C" void kernel_launch(void* const* d_in, const int* in_sizes, int n_in,
                              void* d_out, int out_size) {
    const float* x  = (const float*)d_in[0];
    const float* cf = (const float*)d_in[1];
    const float* bw = (const float*)d_in[2];
    const float* pw = (const float*)d_in[3];
    float* out = (float*)d_out;

    MetaAll m;
    build_meta(m);

    precompute_kernel<<<NGROUPS, 256>>>(cf, bw, pw, m);

    for (int g = 0; g < NGROUPS; ++g) {
        int cs = m.cs[g], k = m.k[g], Tg = m.Tg[g];
        dim3 grid((Tg + 255) / 256, BATCH);
        size_t smem = (size_t)(k * 20 + 256 * cs + k) * sizeof(float);
        conv_kernel<<<grid, 128, smem>>>(x, g, m.off[g], cs, k, Tg);
    }
    for (int g = 0; g < NGROUPS; ++g) {
        int total = BATCH * OUT_T * NPERG;
        size_t smem = (size_t)(m.ws[g] * NPERG) * sizeof(float);
        pool_kernel<<<(total + 255) / 256, 256, smem>>>(
            out, g, m.off[g], m.ps[g], m.ws[g], m.Tg[g], m.a[g]);
    }
}

// round 4
// speedup vs baseline: 1.0742x; 1.0742x over previous
#include <cuda_runtime.h>
#include <math.h>

#define NGROUPS   4
#define NPERG     10
#define NFILT     40
#define TIME_LEN  64000
#define BATCH     32
#define POOLSZ    401
#define POOLSTR   160
#define OUT_T     400
#define MAX_K     512
#define MAX_WS    512
#define TILE      512          // outputs per block (128 threads x 4)

// Scratch (static device globals — allowed; runtime alloc is not)
__device__ float g_kern[NGROUPS][MAX_K * 20];      // [tap][cos f0..9, sin f0..9]
__device__ float g_win [NGROUPS][MAX_WS * NPERG];  // [tap][f]
__device__ float g_mid [4ll * BATCH * TIME_LEN * NPERG];

struct MetaAll {
    int a[4], cs[4], ps[4], k[4], ws[4], Tg[4];
    long long off[4];
};

// ---- packed f32x2 helpers (FFMA2: 2 fp32 FMAs per issue slot) -------------
__device__ __forceinline__ void fma2(unsigned long long& d,
                                     unsigned long long a,
                                     unsigned long long b) {
    asm("fma.rn.f32x2 %0, %1, %2, %0;" : "+l"(d) : "l"(a), "l"(b));
}
__device__ __forceinline__ unsigned long long pack2(float v) {
    unsigned long long r;
    asm("mov.b64 %0, {%1, %1};" : "=l"(r) : "f"(v));
    return r;
}
__device__ __forceinline__ void unpack2(unsigned long long v, float& lo, float& hi) {
    asm("mov.b64 {%0, %1}, %2;" : "=f"(lo), "=f"(hi) : "l"(v));
}

// ---------------------------------------------------------------------------
// Precompute Gabor kernels + pooling windows (double precision: immune to
// fast-math trig at large phase arguments; cost negligible).
// ---------------------------------------------------------------------------
__global__ void precompute_kernel(const float* __restrict__ cf_in,
                                  const float* __restrict__ bw_in,
                                  const float* __restrict__ pw_in,
                                  MetaAll meta) {
    const int g  = blockIdx.x;
    const int a  = meta.a[g];
    const int k  = meta.k[g];
    const int ws = meta.ws[g];
    const int cs = meta.cs[g];
    const double PI = 3.14159265358979323846;
    const double Zd = sqrt(2.0 * log(2.0)) / PI;

    for (int idx = threadIdx.x; idx < k * 20; idx += blockDim.x) {
        int i = idx / 20, j = idx % 20;
        int f = j % 10;
        float cff = fminf(fmaxf(cf_in[a + f], 0.f), (float)PI);
        float bwf = fminf(fmaxf(bw_in[a + f], (float)(2.0 * Zd)), (float)(401.0 * Zd));
        double t  = (double)(i - k / 2);
        double bw = (double)bwf;
        double gauss = exp(-t * t / (2.0 * bw * bw));
        double norm  = 1.0 / (sqrt(2.0 * PI) * bw);
        double ph    = t * (double)cff;
        double v     = norm * gauss * (j < 10 ? cos(ph) : sin(ph));
        g_kern[g][idx] = (float)v;
    }
    for (int idx = threadIdx.x; idx < ws * 10; idx += blockDim.x) {
        int j = idx / 10, f = idx % 10;
        float pwf = fminf(fmaxf(pw_in[a + f], (float)(2.0 / 401.0)), 0.5f);
        double sigma = (double)pwf / (double)cs * 401.0 / (double)ws;
        double hw = 0.5 * (double)(ws - 1);
        double u  = ((double)j - hw) / (sigma * hw);
        g_win[g][idx] = (float)exp(-0.5 * u * u);
    }
}

// ---------------------------------------------------------------------------
// Gabor conv + modulus^2. 128 threads, 512 outputs/block (4 per thread).
// Coefficients read as broadcast ulonglong2 (b64 lanes = adjacent filters);
// all accumulation in packed fma.rn.f32x2.
// ---------------------------------------------------------------------------
__global__ void __launch_bounds__(128) conv_kernel(
        const float* __restrict__ x, int g, long long off,
        int cs, int k, int Tg) {
    extern __shared__ float sm[];
    float* skern = sm;              // k*20 floats (80B per tap, 16B aligned)
    float* sx    = sm + k * 20;     // TILE*cs + k floats

    const int tid = threadIdx.x;
    const int b   = blockIdx.y;
    const int w0  = blockIdx.x * TILE;

    const float* kg = g_kern[g];
    for (int i = tid; i < k * 20; i += 128) skern[i] = kg[i];

    const int nx = TILE * cs + k;
    const float* xb = x + (long long)b * TIME_LEN;
    const int base = w0 * cs - (k >> 1);
    for (int i = tid; i < nx; i += 128) {
        int gx = base + i;
        sx[i] = ((unsigned)gx < (unsigned)TIME_LEN) ? xb[gx] : 0.f;
    }
    __syncthreads();

    unsigned long long acc[4][10];
#pragma unroll
    for (int o = 0; o < 4; ++o)
#pragma unroll
        for (int j = 0; j < 10; ++j) acc[o][j] = 0ull;

    const float* p0 = sx + (tid          ) * cs;
    const float* p1 = sx + (tid + 128    ) * cs;
    const float* p2 = sx + (tid + 256    ) * cs;
    const float* p3 = sx + (tid + 384    ) * cs;

#pragma unroll 2
    for (int i = 0; i < k; ++i) {
        unsigned long long x0 = pack2(p0[i]);
        unsigned long long x1 = pack2(p1[i]);
        unsigned long long x2 = pack2(p2[i]);
        unsigned long long x3 = pack2(p3[i]);
        const ulonglong2* cc = (const ulonglong2*)(skern + i * 20);
#pragma unroll
        for (int q = 0; q < 5; ++q) {
            ulonglong2 c = cc[q];
            fma2(acc[0][2*q  ], x0, c.x);
            fma2(acc[0][2*q+1], x0, c.y);
            fma2(acc[1][2*q  ], x1, c.x);
            fma2(acc[1][2*q+1], x1, c.y);
            fma2(acc[2][2*q  ], x2, c.x);
            fma2(acc[2][2*q+1], x2, c.y);
            fma2(acc[3][2*q  ], x3, c.x);
            fma2(acc[3][2*q+1], x3, c.y);
        }
    }

    float* mid = g_mid + off;
#pragma unroll
    for (int o = 0; o < 4; ++o) {
        int w = w0 + o * 128 + tid;
        if (w < Tg) {
            float* op = mid + ((long long)b * Tg + w) * 10;
#pragma unroll
            for (int j = 0; j < 5; ++j) {
                float c0, c1, s0, s1;
                unpack2(acc[o][j],     c0, c1);   // cos 2j, 2j+1
                unpack2(acc[o][5 + j], s0, s1);   // sin 2j, 2j+1
                op[2*j]     = c0 * c0 + s0 * s0;
                op[2*j + 1] = c1 * c1 + s1 * s1;
            }
        }
    }
}

// ---------------------------------------------------------------------------
// Depthwise Gaussian pooling. One thread per (b, p, f).
// ---------------------------------------------------------------------------
__global__ void pool_kernel(float* __restrict__ out, int g, long long off,
                            int ps, int ws, int Tg, int a) {
    extern __shared__ float swin[];
    const float* wg = g_win[g];
    for (int i = threadIdx.x; i < ws * 10; i += blockDim.x) swin[i] = wg[i];
    __syncthreads();

    int idx = blockIdx.x * blockDim.x + threadIdx.x;
    if (idx >= BATCH * OUT_T * NPERG) return;
    int f = idx % 10;
    int p = (idx / 10) % OUT_T;
    int b = idx / (OUT_T * 10);

    const float* m = g_mid + off + (long long)b * Tg * 10 + f;
    int t0 = p * ps - ws / 2;
    int jlo = (t0 < 0) ? -t0 : 0;
    int jhi = (t0 + ws > Tg) ? (Tg - t0) : ws;
    float acc = 0.f;
    for (int j = jlo; j < jhi; ++j)
        acc = fmaf(swin[j * 10 + f], m[(long long)(t0 + j) * 10], acc);

    out[((long long)b * OUT_T + p) * 40 + a + f] = acc;
}

// ---------------------------------------------------------------------------
// Host: replicate _mel_gabor_init + _group_meta exactly (numpy float64 path,
// cast to float32 where the reference does).
// ---------------------------------------------------------------------------
static void build_meta(MetaAll& m) {
    const double PI = 3.14159265358979323846;
    double freqs[257];
    for (int i = 0; i < 257; ++i) freqs[i] = 8000.0 * (double)i / 256.0;
    auto hz2mel = [](double f) { return 2595.0 * log10(1.0 + f / 700.0); };
    auto mel2hz = [](double mm) { return 700.0 * (pow(10.0, mm / 2595.0) - 1.0); };
    double mlo = hz2mel(60.0), mhi = hz2mel(7800.0);
    double hz[42];
    for (int i = 0; i < 42; ++i) hz[i] = mel2hz(mlo + (mhi - mlo) * (double)i / 41.0);

    const double Zd = sqrt(2.0 * log(2.0)) / PI;
    float cff[NFILT], bwf[NFILT];
    for (int i = 0; i < NFILT; ++i) {
        double l = hz[i], c = hz[i + 1], r = hz[i + 2];
        double peak = -1.0; int cb = 0;
        double vals[257];
        for (int j = 0; j < 257; ++j) {
            double v = (freqs[j] - l) / (c - l);
            double v2 = (r - freqs[j]) / (r - c);
            if (v2 < v) v = v2;
            if (v < 0.0) v = 0.0;
            vals[j] = sqrt(v);
            if (vals[j] > peak) { peak = vals[j]; cb = j; }
        }
        int fwhm = 0;
        for (int j = 0; j < 257; ++j) if (vals[j] >= 0.5 * peak) fwhm++;
        float cfv = (float)((double)cb * 2.0 * PI / 512.0);
        float bwv = (float)(sqrt(2.0 * log(2.0)) * 512.0 / (PI * (double)fwhm));
        cfv = fminf(fmaxf(cfv, 0.f), (float)PI);
        bwv = fminf(fmaxf(bwv, (float)(2.0 * Zd)), (float)(401.0 * Zd));
        cff[i] = cfv; bwf[i] = bwv;
    }

    const int divs[12] = {1, 2, 4, 5, 8, 10, 16, 20, 32, 40, 80, 160};
    long long off = 0;
    for (int g = 0; g < NGROUPS; ++g) {
        int a = g * NPERG, b = a + NPERG;
        float cmax = -1.f, bmax = -1.f;
        for (int i = a; i < b; ++i) {
            if (cff[i] > cmax) cmax = cff[i];
            if (bwf[i] > bmax) bmax = bwf[i];
        }
        double s = PI / (double)cmax;          // STRIDE_FACTOR = 1
        if (s < 1.0) s = 1.0;
        int cs = 1;
        for (int d = 0; d < 12; ++d) if ((double)divs[d] <= s) cs = divs[d];
        int k = (int)((double)bmax * 3.0);
        k += 1 - (k % 2);
        int ws = (int)(401.0 / (double)cs + 0.5);
        ws += 1 - (ws % 2);
        if (k > MAX_K - 1) k = MAX_K - 1;      // never hit: bw clip caps k at 451
        if (ws > MAX_WS - 1) ws = MAX_WS - 1;
        m.a[g] = a; m.cs[g] = cs; m.ps[g] = POOLSTR / cs;
        m.k[g] = k; m.ws[g] = ws; m.Tg[g] = TIME_LEN / cs;
        m.off[g] = off;
        off += (long long)BATCH * (TIME_LEN / cs) * NPERG;
    }
}

extern "C" void kernel_launch(void* const* d_in, const int* in_sizes, int n_in,
                              void* d_out, int out_size) {
    const float* x  = (const float*)d_in[0];
    const float* cf = (const float*)d_in[1];
    const float* bw = (const float*)d_in[2];
    const float* pw = (const float*)d_in[3];
    float* out = (float*)d_out;

    MetaAll m;
    build_meta(m);

    // Worst-case dynamic smem may exceed the 48KB default; set unconditionally
    // (no static guard — deterministic, executes host-side, not captured).
    size_t max_smem = 0;
    for (int g = 0; g < NGROUPS; ++g) {
        size_t s = (size_t)(m.k[g] * 20 + TILE * m.cs[g] + m.k[g]) * sizeof(float);
        if (s > max_smem) max_smem = s;
    }
    cudaFuncSetAttribute(conv_kernel, cudaFuncAttributeMaxDynamicSharedMemorySize,
                         (int)max_smem);

    precompute_kernel<<<NGROUPS, 256>>>(cf, bw, pw, m);

    for (int g = 0; g < NGROUPS; ++g) {
        int cs = m.cs[g], k = m.k[g], Tg = m.Tg[g];
        dim3 grid((Tg + TILE - 1) / TILE, BATCH);
        size_t smem = (size_t)(k * 20 + TILE * cs + k) * sizeof(float);
        conv_kernel<<<grid, 128, smem>>>(x, g, m.off[g], cs, k, Tg);
    }
    for (int g = 0; g < NGROUPS; ++g) {
        int total = BATCH * OUT_T * NPERG;
        size_t smem = (size_t)(m.ws[g] * NPERG) * sizeof(float);
        pool_kernel<<<(total + 255) / 256, 256, smem>>>(
            out, g, m.off[g], m.ps[g], m.ws[g], m.Tg[g], m.a[g]);
    }
}

// round 5
// speedup vs baseline: 1.4113x; 1.3139x over previous
#include <cuda_runtime.h>
#include <math.h>

#define NGROUPS   4
#define NPERG     10
#define NFILT     40
#define TIME_LEN  64000
#define BATCH     32
#define POOLSZ    401
#define POOLSTR   160
#define OUT_T     400
#define MAX_K     512
#define MAX_WS    512
#define TILE      256          // outputs per block (128 threads x 2)

// Scratch (static device globals — allowed; runtime alloc is not)
__device__ float g_kern[NGROUPS][MAX_K * 20];      // folded: [tpair][ (Kc,Ks) x10 ]
__device__ float g_win [NGROUPS][MAX_WS * NPERG];  // [tap][f]
__device__ float g_mid [4ll * BATCH * TIME_LEN * NPERG];

struct MetaAll {
    int a[4], cs[4], ps[4], k[4], ws[4], Tg[4];
    long long off[4];
};

// ---- packed f32x2 helpers --------------------------------------------------
__device__ __forceinline__ void fma2(unsigned long long& d,
                                     unsigned long long a,
                                     unsigned long long b) {
    asm("fma.rn.f32x2 %0, %1, %2, %0;" : "+l"(d) : "l"(a), "l"(b));
}
__device__ __forceinline__ unsigned long long pack2(float v) {
    unsigned long long r;
    asm("mov.b64 %0, {%1, %1};" : "=l"(r) : "f"(v));
    return r;
}
__device__ __forceinline__ unsigned long long packpair(float lo, float hi) {
    unsigned long long r;
    asm("mov.b64 %0, {%1, %2};" : "=l"(r) : "f"(lo), "f"(hi));
    return r;
}
__device__ __forceinline__ unsigned long long add2(unsigned long long a,
                                                   unsigned long long b) {
    unsigned long long r;
    asm("add.rn.f32x2 %0, %1, %2;" : "=l"(r) : "l"(a), "l"(b));
    return r;
}
__device__ __forceinline__ void unpack2(unsigned long long v, float& lo, float& hi) {
    asm("mov.b64 {%0, %1}, %2;" : "=f"(lo), "=f"(hi) : "l"(v));
}

// ---------------------------------------------------------------------------
// Precompute folded Gabor tables + pooling windows (double precision).
// Folded layout: tap-pair t=0..h, 10 interleaved (Kc, Ks) pairs. Ks(0)=0.
// ---------------------------------------------------------------------------
__global__ void precompute_kernel(const float* __restrict__ cf_in,
                                  const float* __restrict__ bw_in,
                                  const float* __restrict__ pw_in,
                                  MetaAll meta) {
    const int g  = blockIdx.x;
    const int a  = meta.a[g];
    const int k  = meta.k[g];
    const int h  = k >> 1;
    const int ws = meta.ws[g];
    const int cs = meta.cs[g];
    const double PI = 3.14159265358979323846;
    const double Zd = sqrt(2.0 * log(2.0)) / PI;

    for (int idx = threadIdx.x; idx < (h + 1) * 20; idx += blockDim.x) {
        int tp = idx / 20, j = idx % 20;
        int f = j >> 1;
        bool is_sin = j & 1;
        float cff = fminf(fmaxf(cf_in[a + f], 0.f), (float)PI);
        float bwf = fminf(fmaxf(bw_in[a + f], (float)(2.0 * Zd)), (float)(401.0 * Zd));
        double t  = (double)tp;
        double bw = (double)bwf;
        double gauss = exp(-t * t / (2.0 * bw * bw));
        double norm  = 1.0 / (sqrt(2.0 * PI) * bw);
        double ph    = t * (double)cff;
        double v     = norm * gauss * (is_sin ? sin(ph) : cos(ph));
        if (is_sin && tp == 0) v = 0.0;
        g_kern[g][idx] = (float)v;
    }
    for (int idx = threadIdx.x; idx < ws * 10; idx += blockDim.x) {
        int j = idx / 10, f = idx % 10;
        float pwf = fminf(fmaxf(pw_in[a + f], (float)(2.0 / 401.0)), 0.5f);
        double sigma = (double)pwf / (double)cs * 401.0 / (double)ws;
        double hw = 0.5 * (double)(ws - 1);
        double u  = ((double)j - hw) / (sigma * hw);
        g_win[g][idx] = (float)exp(-0.5 * u * u);
    }
}

// ---------------------------------------------------------------------------
// Symmetric Gabor conv + modulus^2. 128 threads, 256 outputs/block.
// Per tap-pair t>0: sd = (x+ + x-, x+ - x-) via one add.rn.f32x2;
// acc[f] = (cos_f, sin_f) updated by one fma.rn.f32x2 with coef (Kc, Ks).
// Halves FMA work vs direct conv.
// ---------------------------------------------------------------------------
__global__ void __launch_bounds__(128) conv_kernel(
        const float* __restrict__ x, int g, long long off,
        int cs, int k, int Tg) {
    extern __shared__ float sm[];
    const int h = k >> 1;
    float* skern = sm;                 // (h+1)*20 floats
    float* sx    = sm + (h + 1) * 20;  // TILE*cs + k floats

    const int tid = threadIdx.x;
    const int b   = blockIdx.y;
    const int w0  = blockIdx.x * TILE;

    const float* kg = g_kern[g];
    for (int i = tid; i < (h + 1) * 20; i += 128) skern[i] = kg[i];

    const int nx = TILE * cs + k;
    const float* xb = x + (long long)b * TIME_LEN;
    const int base = w0 * cs - h;
    for (int i = tid; i < nx; i += 128) {
        int gx = base + i;
        sx[i] = ((unsigned)gx < (unsigned)TIME_LEN) ? xb[gx] : 0.f;
    }
    __syncthreads();

    unsigned long long acc[2][10];
#pragma unroll
    for (int o = 0; o < 2; ++o)
#pragma unroll
        for (int j = 0; j < 10; ++j) acc[o][j] = 0ull;

    const float* pc0 = sx + tid * cs + h;            // center of output tid
    const float* pc1 = sx + (tid + 128) * cs + h;    // center of output tid+128

    // center tap (t = 0): coef = (Kc0, 0) -> sin lane accumulates 0
    {
        const ulonglong2* cc = (const ulonglong2*)skern;
        unsigned long long x0 = pack2(pc0[0]);
        unsigned long long x1 = pack2(pc1[0]);
#pragma unroll
        for (int q = 0; q < 5; ++q) {
            ulonglong2 c = cc[q];
            fma2(acc[0][2*q  ], x0, c.x);
            fma2(acc[0][2*q+1], x0, c.y);
            fma2(acc[1][2*q  ], x1, c.x);
            fma2(acc[1][2*q+1], x1, c.y);
        }
    }

#pragma unroll 2
    for (int t = 1; t <= h; ++t) {
        float xp0 = pc0[t],  xm0 = pc0[-t];
        float xp1 = pc1[t],  xm1 = pc1[-t];
        unsigned long long sd0 = add2(pack2(xp0), packpair(xm0, -xm0));
        unsigned long long sd1 = add2(pack2(xp1), packpair(xm1, -xm1));
        const ulonglong2* cc = (const ulonglong2*)(skern + t * 20);
#pragma unroll
        for (int q = 0; q < 5; ++q) {
            ulonglong2 c = cc[q];
            fma2(acc[0][2*q  ], sd0, c.x);
            fma2(acc[0][2*q+1], sd0, c.y);
            fma2(acc[1][2*q  ], sd1, c.x);
            fma2(acc[1][2*q+1], sd1, c.y);
        }
    }

    float* mid = g_mid + off;
#pragma unroll
    for (int o = 0; o < 2; ++o) {
        int w = w0 + o * 128 + tid;
        if (w < Tg) {
            float* op = mid + ((long long)b * Tg + w) * 10;
#pragma unroll
            for (int f = 0; f < 10; ++f) {
                float c, s;
                unpack2(acc[o][f], c, s);
                op[f] = c * c + s * s;
            }
        }
    }
}

// ---------------------------------------------------------------------------
// Depthwise Gaussian pooling: one warp per (b, p). Lanes stride over taps;
// window rows [t][f] are contiguous in memory -> coalesced float2 loads.
// ---------------------------------------------------------------------------
__global__ void pool_kernel(float* __restrict__ out, int g, long long off,
                            int ps, int ws, int Tg, int a) {
    extern __shared__ float swin[];
    const float* wg = g_win[g];
    for (int i = threadIdx.x; i < ws * 10; i += blockDim.x) swin[i] = wg[i];
    __syncthreads();

    int warp = blockIdx.x * (blockDim.x >> 5) + (threadIdx.x >> 5);
    int lane = threadIdx.x & 31;
    if (warp >= BATCH * OUT_T) return;
    int p = warp % OUT_T;
    int b = warp / OUT_T;

    const float* m = g_mid + off + (long long)b * Tg * 10;
    int t0 = p * ps - ws / 2;

    float2 acc2[5];
#pragma unroll
    for (int q = 0; q < 5; ++q) acc2[q] = make_float2(0.f, 0.f);

    for (int j = lane; j < ws; j += 32) {
        int t = t0 + j;
        if ((unsigned)t < (unsigned)Tg) {
            const float2* row = (const float2*)(m + (long long)t * 10);
            const float2* wr  = (const float2*)(swin + j * 10);
#pragma unroll
            for (int q = 0; q < 5; ++q) {
                float2 rv = row[q], wv = wr[q];
                acc2[q].x = fmaf(wv.x, rv.x, acc2[q].x);
                acc2[q].y = fmaf(wv.y, rv.y, acc2[q].y);
            }
        }
    }

#pragma unroll
    for (int o = 16; o; o >>= 1)
#pragma unroll
        for (int q = 0; q < 5; ++q) {
            acc2[q].x += __shfl_down_sync(0xffffffffu, acc2[q].x, o);
            acc2[q].y += __shfl_down_sync(0xffffffffu, acc2[q].y, o);
        }

    if (lane == 0) {
        float* op = out + ((long long)b * OUT_T + p) * 40 + a;
#pragma unroll
        for (int q = 0; q < 5; ++q) {
            op[2*q]     = acc2[q].x;
            op[2*q + 1] = acc2[q].y;
        }
    }
}

// ---------------------------------------------------------------------------
// Host: replicate _mel_gabor_init + _group_meta exactly.
// ---------------------------------------------------------------------------
static void build_meta(MetaAll& m) {
    const double PI = 3.14159265358979323846;
    double freqs[257];
    for (int i = 0; i < 257; ++i) freqs[i] = 8000.0 * (double)i / 256.0;
    auto hz2mel = [](double f) { return 2595.0 * log10(1.0 + f / 700.0); };
    auto mel2hz = [](double mm) { return 700.0 * (pow(10.0, mm / 2595.0) - 1.0); };
    double mlo = hz2mel(60.0), mhi = hz2mel(7800.0);
    double hz[42];
    for (int i = 0; i < 42; ++i) hz[i] = mel2hz(mlo + (mhi - mlo) * (double)i / 41.0);

    const double Zd = sqrt(2.0 * log(2.0)) / PI;
    float cff[NFILT], bwf[NFILT];
    for (int i = 0; i < NFILT; ++i) {
        double l = hz[i], c = hz[i + 1], r = hz[i + 2];
        double peak = -1.0; int cb = 0;
        double vals[257];
        for (int j = 0; j < 257; ++j) {
            double v = (freqs[j] - l) / (c - l);
            double v2 = (r - freqs[j]) / (r - c);
            if (v2 < v) v = v2;
            if (v < 0.0) v = 0.0;
            vals[j] = sqrt(v);
            if (vals[j] > peak) { peak = vals[j]; cb = j; }
        }
        int fwhm = 0;
        for (int j = 0; j < 257; ++j) if (vals[j] >= 0.5 * peak) fwhm++;
        float cfv = (float)((double)cb * 2.0 * PI / 512.0);
        float bwv = (float)(sqrt(2.0 * log(2.0)) * 512.0 / (PI * (double)fwhm));
        cfv = fminf(fmaxf(cfv, 0.f), (float)PI);
        bwv = fminf(fmaxf(bwv, (float)(2.0 * Zd)), (float)(401.0 * Zd));
        cff[i] = cfv; bwf[i] = bwv;
    }

    const int divs[12] = {1, 2, 4, 5, 8, 10, 16, 20, 32, 40, 80, 160};
    long long off = 0;
    for (int g = 0; g < NGROUPS; ++g) {
        int a = g * NPERG, b = a + NPERG;
        float cmax = -1.f, bmax = -1.f;
        for (int i = a; i < b; ++i) {
            if (cff[i] > cmax) cmax = cff[i];
            if (bwf[i] > bmax) bmax = bwf[i];
        }
        double s = PI / (double)cmax;          // STRIDE_FACTOR = 1
        if (s < 1.0) s = 1.0;
        int cs = 1;
        for (int d = 0; d < 12; ++d) if ((double)divs[d] <= s) cs = divs[d];
        int k = (int)((double)bmax * 3.0);
        k += 1 - (k % 2);
        int ws = (int)(401.0 / (double)cs + 0.5);
        ws += 1 - (ws % 2);
        if (k > MAX_K - 1) k = MAX_K - 1;      // never hit: bw clip caps k at 451
        if (ws > MAX_WS - 1) ws = MAX_WS - 1;
        m.a[g] = a; m.cs[g] = cs; m.ps[g] = POOLSTR / cs;
        m.k[g] = k; m.ws[g] = ws; m.Tg[g] = TIME_LEN / cs;
        m.off[g] = off;
        off += (long long)BATCH * (TIME_LEN / cs) * NPERG;
    }
}

extern "C" void kernel_launch(void* const* d_in, const int* in_sizes, int n_in,
                              void* d_out, int out_size) {
    const float* x  = (const float*)d_in[0];
    const float* cf = (const float*)d_in[1];
    const float* bw = (const float*)d_in[2];
    const float* pw = (const float*)d_in[3];
    float* out = (float*)d_out;

    MetaAll m;
    build_meta(m);

    size_t max_smem = 0;
    for (int g = 0; g < NGROUPS; ++g) {
        int h = m.k[g] >> 1;
        size_t s = (size_t)((h + 1) * 20 + TILE * m.cs[g] + m.k[g]) * sizeof(float);
        if (s > max_smem) max_smem = s;
    }
    cudaFuncSetAttribute(conv_kernel, cudaFuncAttributeMaxDynamicSharedMemorySize,
                         (int)max_smem);

    precompute_kernel<<<NGROUPS, 256>>>(cf, bw, pw, m);

    for (int g = 0; g < NGROUPS; ++g) {
        int cs = m.cs[g], k = m.k[g], Tg = m.Tg[g];
        int h = k >> 1;
        dim3 grid((Tg + TILE - 1) / TILE, BATCH);
        size_t smem = (size_t)((h + 1) * 20 + TILE * cs + k) * sizeof(float);
        conv_kernel<<<grid, 128, smem>>>(x, g, m.off[g], cs, k, Tg);
    }
    for (int g = 0; g < NGROUPS; ++g) {
        int nwarps = BATCH * OUT_T;              // 12800
        int blocks = (nwarps + 7) / 8;           // 8 warps per 256-thread block
        size_t smem = (size_t)(m.ws[g] * NPERG) * sizeof(float);
        pool_kernel<<<blocks, 256, smem>>>(
            out, g, m.off[g], m.ps[g], m.ws[g], m.Tg[g], m.a[g]);
    }
}